// round 15
// baseline (speedup 1.0000x reference)
#include <cuda_runtime.h>
#include <cuda_fp16.h>
#include <cstdint>

#define NN 100000
#define EE 1600000
#define NG 64
#define NH 10

// ---------------- constant weights (filled via capturable D2D memcpy) ----------------
__constant__ float c_e1W[1600];   // [50][32]
__constant__ float c_e2W[320];    // [10][32]

// ---------------- scratch (__device__ globals; no cudaMalloc allowed) ----------------
__device__ __align__(16) float g_w1[160 * 128];      // packed [q1;k1;v1;s1;pad] x 128
__device__ float g_b1[160];
__device__ __align__(16) float g_w2[160];            // packed 31x5 (q2,k2,v2,s2)
__device__ float g_b2[32];
// conv1 node table, fp16: per node stride 192 halves: q@0(50), k@64(50), v@128(50)
__device__ __align__(16) __half g_nlh[(size_t)NN * 192];
__device__ float g_xr1[NN * 5];                      // conv1 skip (fp32)
// conv2 edge bias, fp16 interleaved: per edge 16 halves (32B), e2 in [0..9]
__device__ __align__(16) __half g_e2h[(size_t)EE * 16];
// conv1 accumulators: A[n][h][4] = num0..3 ; B[n][h*2,(h*2)+1] = (num4, den), 24 floats/n
__device__ __align__(16) float g_acc1A[(size_t)NN * 40];
__device__ __align__(16) float g_acc1B[(size_t)NN * 24];
__device__ float g_h1[NN * 5];
// conv2 node table fp16, one 128B line per node: q@0(10), k@16(10), v@32(10), 64 halves
__device__ __align__(16) __half g_nl2h[(size_t)NN * 64];
__device__ float g_xr2[NN];                          // conv2 skip (fp32)
// conv2 accumulator pairs: [n][h*2]=num, [n][h*2+1]=den, 24 floats/n (20 used)
__device__ __align__(16) float g_acc2p[(size_t)NN * 24];
__device__ float g_gsum[NG * 8];                     // sums(5), count at [5]
__device__ float g_gvar[NG * 8];

// ---------------- helpers ----------------
__device__ __forceinline__ void redAdd4(float* p, float a, float b, float c, float d) {
    asm volatile("red.global.add.v4.f32 [%0], {%1, %2, %3, %4};"
                 :: "l"(p), "f"(a), "f"(b), "f"(c), "f"(d) : "memory");
}
__device__ __forceinline__ void redAdd2(float* p, float a, float b) {
    asm volatile("red.global.add.v2.f32 [%0], {%1, %2};"
                 :: "l"(p), "f"(a), "f"(b) : "memory");
}
// packed f32x2 dot product over 32 constant-bank weights vs packed ea pairs
__device__ __forceinline__ float cdot32(const float* cw, const unsigned long long* ea2) {
    unsigned long long acc = 0ull;  // packed {0.f, 0.f}
#pragma unroll
    for (int t = 0; t < 16; ++t) {
        unsigned long long w = *reinterpret_cast<const unsigned long long*>(cw + 2 * t);
        asm("fma.rn.f32x2 %0, %1, %2, %3;" : "=l"(acc) : "l"(w), "l"(ea2[t]), "l"(acc));
    }
    float lo, hi;
    asm("mov.b64 {%0, %1}, %2;" : "=f"(lo), "=f"(hi) : "l"(acc));
    return lo + hi;
}
// load 32 halves (4x LDG.128) starting at 16B-aligned p, convert to float
__device__ __forceinline__ void ldh32(const __half* p, float* out) {
#pragma unroll
    for (int t = 0; t < 4; ++t) {
        uint4 r = *(const uint4*)(p + t * 8);
        const __half2* h2 = (const __half2*)&r;
#pragma unroll
        for (int j = 0; j < 4; ++j) {
            float2 f = __half22float2(h2[j]);
            out[t * 8 + 2 * j] = f.x;
            out[t * 8 + 2 * j + 1] = f.y;
        }
    }
}
// load 16 halves (2x LDG.128) from 32B-aligned p, convert to float
__device__ __forceinline__ void ldh16(const __half* p, float* out) {
#pragma unroll
    for (int t = 0; t < 2; ++t) {
        uint4 r = *(const uint4*)(p + t * 8);
        const __half2* h2 = (const __half2*)&r;
#pragma unroll
        for (int j = 0; j < 4; ++j) {
            float2 f = __half22float2(h2[j]);
            out[t * 8 + 2 * j] = f.x;
            out[t * 8 + 2 * j + 1] = f.y;
        }
    }
}

// ---------------- K0: pack weights ----------------
__global__ void k_pack(const float* q1W, const float* q1b, const float* k1W, const float* k1b,
                       const float* v1W, const float* v1b, const float* s1W, const float* s1b,
                       const float* q2W, const float* q2b, const float* k2W, const float* k2b,
                       const float* v2W, const float* v2b, const float* s2W, const float* s2b) {
    int tid = blockIdx.x * blockDim.x + threadIdx.x;
    int stride = gridDim.x * blockDim.x;
    for (int i = tid; i < 160 * 128; i += stride) {
        int o = i >> 7, k = i & 127;
        float v = 0.f;
        if (o < 50) v = q1W[o * 128 + k];
        else if (o < 100) v = k1W[(o - 50) * 128 + k];
        else if (o < 150) v = v1W[(o - 100) * 128 + k];
        else if (o < 155) v = s1W[(o - 150) * 128 + k];
        g_w1[i] = v;
    }
    for (int o = tid; o < 160; o += stride) {
        float b = 0.f;
        if (o < 50) b = q1b[o];
        else if (o < 100) b = k1b[o - 50];
        else if (o < 150) b = v1b[o - 100];
        else if (o < 155) b = s1b[o - 150];
        g_b1[o] = b;
    }
    for (int i = tid; i < 31 * 5; i += stride) {
        int o = i / 5, c = i % 5;
        float v;
        if (o < 10) v = q2W[o * 5 + c];
        else if (o < 20) v = k2W[(o - 10) * 5 + c];
        else if (o < 30) v = v2W[(o - 20) * 5 + c];
        else v = s2W[c];
        g_w2[i] = v;
    }
    for (int o = tid; o < 31; o += stride) {
        float b;
        if (o < 10) b = q2b[o];
        else if (o < 20) b = k2b[o - 10];
        else if (o < 30) b = v2b[o - 20];
        else b = s2b[0];
        g_b2[o] = b;
    }
}

// ---------------- K_init: zero accumulators (every launch, deterministic) ----------------
__global__ void k_init() {
    int tid = blockIdx.x * blockDim.x + threadIdx.x;
    int stride = gridDim.x * blockDim.x;
    float4 z = make_float4(0.f, 0.f, 0.f, 0.f);
    float4* a = (float4*)g_acc1A;     // 1,000,000 float4
    for (int i = tid; i < NN * 10; i += stride) a[i] = z;
    float4* b = (float4*)g_acc1B;     // 600,000 float4
    for (int i = tid; i < NN * 6; i += stride) b[i] = z;
    float4* c = (float4*)g_acc2p;     // 600,000 float4
    for (int i = tid; i < NN * 6; i += stride) c[i] = z;
    for (int i = tid; i < NG * 8; i += stride) { g_gsum[i] = 0.f; g_gvar[i] = 0.f; }
}

// ---------------- K1: node linear 1 (GEMM 100000 x 155 x 128) ----------------
__global__ void k_lin1(const float* __restrict__ x) {
    __shared__ float Xs[16][64];    // [k][node]
    __shared__ float Ws[16][160];   // [k][out]
    int tid = threadIdx.x;
    int nb = blockIdx.x * 64;
    int ni = tid & 15, oi = tid >> 4;
    float acc[4][10];
#pragma unroll
    for (int i = 0; i < 4; ++i)
#pragma unroll
        for (int j = 0; j < 10; ++j) acc[i][j] = 0.f;

    for (int kt = 0; kt < 8; ++kt) {
        {
            int i = tid >> 2, kq = tid & 3;
            int node = nb + i;
            float4 xv = make_float4(0.f, 0.f, 0.f, 0.f);
            if (node < NN) xv = *(const float4*)&x[(size_t)node * 128 + kt * 16 + kq * 4];
            Xs[kq * 4 + 0][i] = xv.x;
            Xs[kq * 4 + 1][i] = xv.y;
            Xs[kq * 4 + 2][i] = xv.z;
            Xs[kq * 4 + 3][i] = xv.w;
        }
#pragma unroll
        for (int r = 0; r < 10; ++r) {
            int idx = tid + r * 256;
            int o = idx >> 4, k = idx & 15;
            Ws[k][o] = g_w1[o * 128 + kt * 16 + k];
        }
        __syncthreads();
#pragma unroll 4
        for (int k = 0; k < 16; ++k) {
            float4 xv = *(const float4*)&Xs[k][ni * 4];
            float xs[4] = {xv.x, xv.y, xv.z, xv.w};
#pragma unroll
            for (int j = 0; j < 10; ++j) {
                float w = Ws[k][oi * 10 + j];
#pragma unroll
                for (int i2 = 0; i2 < 4; ++i2) acc[i2][j] = fmaf(xs[i2], w, acc[i2][j]);
            }
        }
        __syncthreads();
    }
#pragma unroll
    for (int i2 = 0; i2 < 4; ++i2) {
        int node = nb + ni * 4 + i2;
        if (node < NN) {
#pragma unroll
            for (int j = 0; j < 10; ++j) {
                int o = oi * 10 + j;
                float val = acc[i2][j] + g_b1[o];
                if (o < 150) {
                    int sec = o >= 100 ? 2 : (o >= 50 ? 1 : 0);
                    int idx = o - sec * 50;
                    g_nlh[(size_t)node * 192 + sec * 64 + idx] = __float2half_rn(val);
                } else if (o < 155) {
                    g_xr1[node * 5 + (o - 150)] = val;
                }
            }
        }
    }
}

// ---------------- K2: conv1 fused edge pass (vector staging + f32x2 GEMM) -------------
// sEA stride = 36 floats/edge (144B): 16B-aligned for STS/LDS.128, and 36 mod 32 = 4
// banks apart per lane so both .128 store (contiguous 128B per 8-lane phase) and load
// (8 lanes x 4 distinct banks) are conflict-free.
__global__ __launch_bounds__(256) void k_edge1(const float* __restrict__ ea_g,
                                               const int* __restrict__ eidx) {
    __shared__ __align__(16) float sEA[256 * 36];
    int tid = threadIdx.x;
    int e0 = blockIdx.x * 256;
    {
        const float4* ea4 = (const float4*)(ea_g + (size_t)e0 * 32);
#pragma unroll
        for (int t = 0; t < 8; ++t) {
            int i = tid + t * 256;            // 2048 float4 per block
            float4 v = __ldcs(&ea4[i]);
            int edge = i >> 3, q = i & 7;
            *(float4*)&sEA[edge * 36 + q * 4] = v;
        }
    }
    __syncthreads();
    int e = e0 + tid;              // EE == 6250*256, no partial block
    int src = eidx[e], dst = eidx[EE + e];
    // ea as 16 packed f32x2 pairs, via 8 LDS.128
    unsigned long long ea2[16];
#pragma unroll
    for (int q = 0; q < 8; ++q) {
        float4 v = *(const float4*)&sEA[tid * 36 + q * 4];
        asm("mov.b64 %0, {%1, %2};" : "=l"(ea2[2 * q]) : "f"(v.x), "f"(v.y));
        asm("mov.b64 %0, {%1, %2};" : "=l"(ea2[2 * q + 1]) : "f"(v.z), "f"(v.w));
    }

    // e2 for conv2 -> fp16 interleaved (32B per edge, 2x STG.128)
    {
        __half2 hp[8];
        float prev = 0.f;
#pragma unroll
        for (int h = 0; h < NH; ++h) {
            float a = cdot32(&c_e2W[h * 32], ea2);
            if (h & 1) hp[h >> 1] = __floats2half2_rn(prev, a);
            prev = a;
        }
        hp[5] = __floats2half2_rn(0.f, 0.f);
        hp[6] = hp[5];
        hp[7] = hp[5];
        const uint4* pw = (const uint4*)hp;
        uint4* dstp = (uint4*)(g_e2h + (size_t)e * 16);
        __stcs(dstp, pw[0]);
        __stcs(dstp + 1, pw[1]);
    }

    const __half* hq = g_nlh + (size_t)dst * 192;        // q @ 0
    const __half* hk = g_nlh + (size_t)src * 192 + 64;   // k @ 64
    const __half* hv = g_nlh + (size_t)src * 192 + 128;  // v @ 128

#pragma unroll
    for (int ch = 0; ch < 2; ++ch) {
        const int s0 = (ch == 0) ? 0 : 24;  // first half index of 32-half window (16B aligned)
        const int h0 = ch * 5;
        // e1 for heads h0..h0+4 (constant-bank weights, packed f32x2 MACs)
        float e1c[25];
#pragma unroll
        for (int i = 0; i < 25; ++i)
            e1c[i] = cdot32(&c_e1W[(h0 * 5 + i) * 32], ea2);
        float ex[5];
        {
            float qa[32], ka[32];
            ldh32(hq + s0, qa);
            ldh32(hk + s0, ka);
#pragma unroll
            for (int hc = 0; hc < 5; ++hc) {
                int li0 = (h0 + hc) * 5 - s0;
                float a = 0.f;
#pragma unroll
                for (int c = 0; c < 5; ++c)
                    a = fmaf(qa[li0 + c], ka[li0 + c] + e1c[hc * 5 + c], a);
                ex[hc] = __expf(a * 0.4472135954999579f);  // 1/sqrt(5); no max: exp safe
            }
        }
        {
            float va[32];
            ldh32(hv + s0, va);
            float n4s[5];
#pragma unroll
            for (int hc = 0; hc < 5; ++hc) {
                int li0 = (h0 + hc) * 5 - s0;
                float n0 = ex[hc] * (va[li0 + 0] + e1c[hc * 5 + 0]);
                float n1 = ex[hc] * (va[li0 + 1] + e1c[hc * 5 + 1]);
                float n2 = ex[hc] * (va[li0 + 2] + e1c[hc * 5 + 2]);
                float n3 = ex[hc] * (va[li0 + 3] + e1c[hc * 5 + 3]);
                n4s[hc]  = ex[hc] * (va[li0 + 4] + e1c[hc * 5 + 4]);
                redAdd4(&g_acc1A[((size_t)dst * NH + h0 + hc) * 4], n0, n1, n2, n3);
            }
            float* B = g_acc1B + (size_t)dst * 24;
            if (ch == 0) {
                redAdd4(B + 0, n4s[0], ex[0], n4s[1], ex[1]);   // heads 0,1
                redAdd4(B + 4, n4s[2], ex[2], n4s[3], ex[3]);   // heads 2,3
                redAdd2(B + 8, n4s[4], ex[4]);                  // head 4
            } else {
                redAdd2(B + 10, n4s[0], ex[0]);                 // head 5
                redAdd4(B + 12, n4s[1], ex[1], n4s[2], ex[2]);  // heads 6,7
                redAdd4(B + 16, n4s[3], ex[3], n4s[4], ex[4]);  // heads 8,9
            }
        }
    }
}

// ---------------- K3: conv1 node finish (head mean, beta gate) + GN sums ----------------
__global__ void k_node1(const float* __restrict__ b1W, const int* __restrict__ batch) {
    int n = blockIdx.x * 256 + threadIdx.x;
    if (n >= NN) return;
    float out[5] = {0.f, 0.f, 0.f, 0.f, 0.f};
    const float* A = g_acc1A + (size_t)n * 40;
    const float* B = g_acc1B + (size_t)n * 24;
#pragma unroll
    for (int h = 0; h < NH; ++h) {
        float d = B[h * 2 + 1];
        float inv = d > 0.f ? 1.f / d : 0.f;
#pragma unroll
        for (int c = 0; c < 4; ++c) out[c] += A[h * 4 + c] * inv;
        out[4] += B[h * 2] * inv;
    }
    float xr[5];
#pragma unroll
    for (int c = 0; c < 5; ++c) { out[c] *= 0.1f; xr[c] = g_xr1[n * 5 + c]; }
    float z = 0.f;
#pragma unroll
    for (int c = 0; c < 5; ++c)
        z += out[c] * b1W[c] + xr[c] * b1W[5 + c] + (out[c] - xr[c]) * b1W[10 + c];
    float beta = 1.f / (1.f + __expf(-z));
    int g = batch[n];
#pragma unroll
    for (int c = 0; c < 5; ++c) {
        float hv = beta * xr[c] + (1.f - beta) * out[c];
        g_h1[n * 5 + c] = hv;
        atomicAdd(&g_gsum[g * 8 + c], hv);
    }
    atomicAdd(&g_gsum[g * 8 + 5], 1.f);
}

// ---------------- K4: GraphNorm center + var sums ----------------
__global__ void k_gn_var(const int* __restrict__ batch, const float* __restrict__ gnms) {
    int n = blockIdx.x * 256 + threadIdx.x;
    if (n >= NN) return;
    int g = batch[n];
    float cnt = fmaxf(g_gsum[g * 8 + 5], 1.f);
    float inv = 1.f / cnt;
#pragma unroll
    for (int c = 0; c < 5; ++c) {
        float mean = g_gsum[g * 8 + c] * inv;
        float t = g_h1[n * 5 + c] - mean * gnms[c];
        g_h1[n * 5 + c] = t;
        atomicAdd(&g_gvar[g * 8 + c], t * t);
    }
}

// ---------------- K5: GraphNorm apply + ReLU + node linear 2 (fp16 table) --------------
__global__ void k_node2(const int* __restrict__ batch, const float* __restrict__ gnW,
                        const float* __restrict__ gnb) {
    __shared__ float sw[160];
    __shared__ float sb[32];
    int tid = threadIdx.x;
    if (tid < 155) sw[tid] = g_w2[tid];
    if (tid < 31) sb[tid] = g_b2[tid];
    __syncthreads();
    int n = blockIdx.x * 256 + tid;
    if (n >= NN) return;
    int g = batch[n];
    float cnt = fmaxf(g_gsum[g * 8 + 5], 1.f);
    float hn[5];
#pragma unroll
    for (int c = 0; c < 5; ++c) {
        float var = g_gvar[g * 8 + c] / cnt;
        float t = g_h1[n * 5 + c];
        float y = gnW[c] * t * rsqrtf(var + 1e-5f) + gnb[c];
        hn[c] = fmaxf(y, 0.f);
    }
    __half* nt = g_nl2h + (size_t)n * 64;
#pragma unroll
    for (int o = 0; o < 31; ++o) {
        float a = sb[o];
#pragma unroll
        for (int c = 0; c < 5; ++c) a = fmaf(sw[o * 5 + c], hn[c], a);
        if (o < 30) {
            int slot = o < 10 ? o : (o < 20 ? o + 6 : o + 12);  // q@0, k@16, v@32
            nt[slot] = __float2half_rn(a);
        } else {
            g_xr2[n] = a;
        }
    }
}

// ---------------- K6: conv2 fused edge pass (fp16 table + fp16 e2, 5 REDs) -------------
__global__ __launch_bounds__(256) void k_edge2(const int* __restrict__ eidx) {
    int e = blockIdx.x * 256 + threadIdx.x;
    int src = eidx[e], dst = eidx[EE + e];
    float qa[16], ka[16], va[16], ez[16];
    ldh16(g_nl2h + (size_t)dst * 64, qa);        // q line of dst
    ldh16(g_nl2h + (size_t)src * 64 + 16, ka);   // k of src
    ldh16(g_nl2h + (size_t)src * 64 + 32, va);   // v of src (same 128B line as k)
    {
        const uint4* ep = (const uint4*)(g_e2h + (size_t)e * 16);
        uint4 r0 = __ldcs(ep);
        uint4 r1 = __ldcs(ep + 1);
        const __half2* h0 = (const __half2*)&r0;
        const __half2* h1 = (const __half2*)&r1;
#pragma unroll
        for (int j = 0; j < 4; ++j) {
            float2 f = __half22float2(h0[j]);
            ez[2 * j] = f.x; ez[2 * j + 1] = f.y;
            float2 g = __half22float2(h1[j]);
            ez[8 + 2 * j] = g.x; ez[8 + 2 * j + 1] = g.y;
        }
    }
    float* acc = g_acc2p + (size_t)dst * 24;
#pragma unroll
    for (int h = 0; h < NH; h += 2) {
        float ex0 = __expf(qa[h] * (ka[h] + ez[h]));          // c=1 scale; exp safe
        float n0 = ex0 * (va[h] + ez[h]);
        float ex1 = __expf(qa[h + 1] * (ka[h + 1] + ez[h + 1]));
        float n1 = ex1 * (va[h + 1] + ez[h + 1]);
        redAdd4(acc + h * 2, n0, ex0, n1, ex1);
    }
}

// ---------------- K7: final (head mean, beta gate, sigmoid) ----------------
__global__ void k_final(const float* __restrict__ b2W, float* __restrict__ outp) {
    int n = blockIdx.x * 256 + threadIdx.x;
    if (n >= NN) return;
    float s = 0.f;
    const float* acc = g_acc2p + (size_t)n * 24;
#pragma unroll
    for (int h = 0; h < NH; ++h) {
        float num = acc[h * 2 + 0];
        float d = acc[h * 2 + 1];
        s += d > 0.f ? num / d : 0.f;
    }
    float out = s * 0.1f;
    float xr = g_xr2[n];
    float z = out * b2W[0] + xr * b2W[1] + (out - xr) * b2W[2];
    float beta = 1.f / (1.f + __expf(-z));
    float y = beta * xr + (1.f - beta) * out;
    outp[n] = 1.f / (1.f + __expf(-y));
}

// ---------------- launch ----------------
extern "C" void kernel_launch(void* const* d_in, const int* in_sizes, int n_in,
                              void* d_out, int out_size) {
    (void)in_sizes; (void)n_in; (void)out_size;
    const float* x    = (const float*)d_in[0];
    const float* ea   = (const float*)d_in[1];
    const int*   eidx = (const int*)d_in[2];
    const int*   batch= (const int*)d_in[3];
    const float* q1W = (const float*)d_in[4];  const float* q1b = (const float*)d_in[5];
    const float* k1W = (const float*)d_in[6];  const float* k1b = (const float*)d_in[7];
    const float* v1W = (const float*)d_in[8];  const float* v1b = (const float*)d_in[9];
    const float* e1W = (const float*)d_in[10];
    const float* s1W = (const float*)d_in[11]; const float* s1b = (const float*)d_in[12];
    const float* b1W = (const float*)d_in[13];
    const float* gnW = (const float*)d_in[14]; const float* gnb = (const float*)d_in[15];
    const float* gnms= (const float*)d_in[16];
    const float* q2W = (const float*)d_in[17]; const float* q2b = (const float*)d_in[18];
    const float* k2W = (const float*)d_in[19]; const float* k2b = (const float*)d_in[20];
    const float* v2W = (const float*)d_in[21]; const float* v2b = (const float*)d_in[22];
    const float* e2W = (const float*)d_in[23];
    const float* s2W = (const float*)d_in[24]; const float* s2b = (const float*)d_in[25];
    const float* b2W = (const float*)d_in[26];
    float* outp = (float*)d_out;

    // fill constant bank (graph-capturable D2D memcpy nodes)
    cudaMemcpyToSymbolAsync(c_e1W, e1W, 1600 * sizeof(float), 0, cudaMemcpyDeviceToDevice);
    cudaMemcpyToSymbolAsync(c_e2W, e2W, 320 * sizeof(float), 0, cudaMemcpyDeviceToDevice);

    k_pack<<<80, 256>>>(q1W, q1b, k1W, k1b, v1W, v1b, s1W, s1b,
                        q2W, q2b, k2W, k2b, v2W, v2b, s2W, s2b);
    k_init<<<2048, 256>>>();
    k_lin1<<<(NN + 63) / 64, 256>>>(x);
    k_edge1<<<EE / 256, 256>>>(ea, eidx);
    k_node1<<<(NN + 255) / 256, 256>>>(b1W, batch);
    k_gn_var<<<(NN + 255) / 256, 256>>>(batch, gnms);
    k_node2<<<(NN + 255) / 256, 256>>>(batch, gnW, gnb);
    k_edge2<<<EE / 256, 256>>>(eidx);
    k_final<<<(NN + 255) / 256, 256>>>(b2W, outp);
}

// round 17
// speedup vs baseline: 1.6265x; 1.6265x over previous
#include <cuda_runtime.h>
#include <cuda_fp16.h>
#include <cstdint>

#define NN 100000
#define EE 1600000
#define NG 64
#define NH 10

// ---------------- constant weights (filled via capturable D2D memcpy) ----------------
__constant__ float c_e1W[1600];   // [50][32]
__constant__ float c_e2W[320];    // [10][32]

// ---------------- scratch (__device__ globals; no cudaMalloc allowed) ----------------
__device__ __align__(16) float g_w1[160 * 128];      // packed [q1;k1;v1;s1;pad] x 128
__device__ float g_b1[160];
__device__ __align__(16) float g_w2[160];            // packed 31x5 (q2,k2,v2,s2)
__device__ float g_b2[32];
// conv1 node table, fp16: per node stride 192 halves: q@0(50), k@64(50), v@128(50)
__device__ __align__(16) __half g_nlh[(size_t)NN * 192];
__device__ float g_xr1[NN * 5];                      // conv1 skip (fp32)
// conv2 edge bias, fp16 interleaved: per edge 16 halves (32B), e2 in [0..9]
__device__ __align__(16) __half g_e2h[(size_t)EE * 16];
// conv1 accumulators: A[n][h][4] = num0..3 ; B[n][h*2,(h*2)+1] = (num4, den), 24 floats/n
__device__ __align__(16) float g_acc1A[(size_t)NN * 40];
__device__ __align__(16) float g_acc1B[(size_t)NN * 24];
__device__ float g_h1[NN * 5];
// conv2 node table fp16, one 128B line per node: q@0(10), kv@16(20: k 16..25, v 26..35)
__device__ __align__(16) __half g_nl2h[(size_t)NN * 64];
__device__ float g_xr2[NN];                          // conv2 skip (fp32)
// conv2 accumulator pairs: [n][h*2]=num, [n][h*2+1]=den, 24 floats/n (20 used)
__device__ __align__(16) float g_acc2p[(size_t)NN * 24];
__device__ float g_gsum[NG * 8];                     // sums(5), count at [5]
__device__ float g_gvar[NG * 8];

// ---------------- helpers ----------------
__device__ __forceinline__ void redAdd4(float* p, float a, float b, float c, float d) {
    asm volatile("red.global.add.v4.f32 [%0], {%1, %2, %3, %4};"
                 :: "l"(p), "f"(a), "f"(b), "f"(c), "f"(d) : "memory");
}
__device__ __forceinline__ void redAdd2(float* p, float a, float b) {
    asm volatile("red.global.add.v2.f32 [%0], {%1, %2};"
                 :: "l"(p), "f"(a), "f"(b) : "memory");
}
// packed f32x2 dot product over 32 constant-bank weights vs packed ea pairs
__device__ __forceinline__ float cdot32(const float* cw, const unsigned long long* ea2) {
    unsigned long long acc = 0ull;  // packed {0.f, 0.f}
#pragma unroll
    for (int t = 0; t < 16; ++t) {
        unsigned long long w = *reinterpret_cast<const unsigned long long*>(cw + 2 * t);
        asm("fma.rn.f32x2 %0, %1, %2, %3;" : "=l"(acc) : "l"(w), "l"(ea2[t]), "l"(acc));
    }
    float lo, hi;
    asm("mov.b64 {%0, %1}, %2;" : "=f"(lo), "=f"(hi) : "l"(acc));
    return lo + hi;
}
// load 32 halves (4x LDG.128) starting at 16B-aligned p, convert to float
__device__ __forceinline__ void ldh32(const __half* p, float* out) {
#pragma unroll
    for (int t = 0; t < 4; ++t) {
        uint4 r = *(const uint4*)(p + t * 8);
        const __half2* h2 = (const __half2*)&r;
#pragma unroll
        for (int j = 0; j < 4; ++j) {
            float2 f = __half22float2(h2[j]);
            out[t * 8 + 2 * j] = f.x;
            out[t * 8 + 2 * j + 1] = f.y;
        }
    }
}
// load 16 halves (2x LDG.128) from 32B-aligned p, convert to float
__device__ __forceinline__ void ldh16(const __half* p, float* out) {
#pragma unroll
    for (int t = 0; t < 2; ++t) {
        uint4 r = *(const uint4*)(p + t * 8);
        const __half2* h2 = (const __half2*)&r;
#pragma unroll
        for (int j = 0; j < 4; ++j) {
            float2 f = __half22float2(h2[j]);
            out[t * 8 + 2 * j] = f.x;
            out[t * 8 + 2 * j + 1] = f.y;
        }
    }
}
// load 24 halves (3x LDG.128) from 32B-aligned p, convert to float
__device__ __forceinline__ void ldh24(const __half* p, float* out) {
#pragma unroll
    for (int t = 0; t < 3; ++t) {
        uint4 r = *(const uint4*)(p + t * 8);
        const __half2* h2 = (const __half2*)&r;
#pragma unroll
        for (int j = 0; j < 4; ++j) {
            float2 f = __half22float2(h2[j]);
            out[t * 8 + 2 * j] = f.x;
            out[t * 8 + 2 * j + 1] = f.y;
        }
    }
}

// ---------------- K0: pack weights ----------------
__global__ void k_pack(const float* q1W, const float* q1b, const float* k1W, const float* k1b,
                       const float* v1W, const float* v1b, const float* s1W, const float* s1b,
                       const float* q2W, const float* q2b, const float* k2W, const float* k2b,
                       const float* v2W, const float* v2b, const float* s2W, const float* s2b) {
    int tid = blockIdx.x * blockDim.x + threadIdx.x;
    int stride = gridDim.x * blockDim.x;
    for (int i = tid; i < 160 * 128; i += stride) {
        int o = i >> 7, k = i & 127;
        float v = 0.f;
        if (o < 50) v = q1W[o * 128 + k];
        else if (o < 100) v = k1W[(o - 50) * 128 + k];
        else if (o < 150) v = v1W[(o - 100) * 128 + k];
        else if (o < 155) v = s1W[(o - 150) * 128 + k];
        g_w1[i] = v;
    }
    for (int o = tid; o < 160; o += stride) {
        float b = 0.f;
        if (o < 50) b = q1b[o];
        else if (o < 100) b = k1b[o - 50];
        else if (o < 150) b = v1b[o - 100];
        else if (o < 155) b = s1b[o - 150];
        g_b1[o] = b;
    }
    for (int i = tid; i < 31 * 5; i += stride) {
        int o = i / 5, c = i % 5;
        float v;
        if (o < 10) v = q2W[o * 5 + c];
        else if (o < 20) v = k2W[(o - 10) * 5 + c];
        else if (o < 30) v = v2W[(o - 20) * 5 + c];
        else v = s2W[c];
        g_w2[i] = v;
    }
    for (int o = tid; o < 31; o += stride) {
        float b;
        if (o < 10) b = q2b[o];
        else if (o < 20) b = k2b[o - 10];
        else if (o < 30) b = v2b[o - 20];
        else b = s2b[0];
        g_b2[o] = b;
    }
}

// ---------------- K_init: zero accumulators (every launch, deterministic) ----------------
__global__ void k_init() {
    int tid = blockIdx.x * blockDim.x + threadIdx.x;
    int stride = gridDim.x * blockDim.x;
    float4 z = make_float4(0.f, 0.f, 0.f, 0.f);
    float4* a = (float4*)g_acc1A;     // 1,000,000 float4
    for (int i = tid; i < NN * 10; i += stride) a[i] = z;
    float4* b = (float4*)g_acc1B;     // 600,000 float4
    for (int i = tid; i < NN * 6; i += stride) b[i] = z;
    float4* c = (float4*)g_acc2p;     // 600,000 float4
    for (int i = tid; i < NN * 6; i += stride) c[i] = z;
    for (int i = tid; i < NG * 8; i += stride) { g_gsum[i] = 0.f; g_gvar[i] = 0.f; }
}

// ---------------- K1: node linear 1 (GEMM 100000 x 155 x 128, f32x2 packed) -----------
__global__ void k_lin1(const float* __restrict__ x) {
    __shared__ __align__(16) float Xs[16][64];    // [k][node]
    __shared__ __align__(16) float Ws[16][160];   // [k][out]
    int tid = threadIdx.x;
    int nb = blockIdx.x * 64;
    int ni = tid & 15, oi = tid >> 4;
    // acc packed over adjacent output pairs: accp[i2][j2] = {acc[i2][2j2], acc[i2][2j2+1]}
    unsigned long long accp[4][5];
#pragma unroll
    for (int i = 0; i < 4; ++i)
#pragma unroll
        for (int j = 0; j < 5; ++j) accp[i][j] = 0ull;

    for (int kt = 0; kt < 8; ++kt) {
        {
            int i = tid >> 2, kq = tid & 3;
            int node = nb + i;
            float4 xv = make_float4(0.f, 0.f, 0.f, 0.f);
            if (node < NN) xv = *(const float4*)&x[(size_t)node * 128 + kt * 16 + kq * 4];
            Xs[kq * 4 + 0][i] = xv.x;
            Xs[kq * 4 + 1][i] = xv.y;
            Xs[kq * 4 + 2][i] = xv.z;
            Xs[kq * 4 + 3][i] = xv.w;
        }
#pragma unroll
        for (int r = 0; r < 10; ++r) {
            int idx = tid + r * 256;
            int o = idx >> 4, k = idx & 15;
            Ws[k][o] = g_w1[o * 128 + kt * 16 + k];
        }
        __syncthreads();
#pragma unroll 4
        for (int k = 0; k < 16; ++k) {
            float4 xv = *(const float4*)&Xs[k][ni * 4];
            unsigned long long xp[4];
            asm("mov.b64 %0, {%1, %1};" : "=l"(xp[0]) : "f"(xv.x));
            asm("mov.b64 %0, {%1, %1};" : "=l"(xp[1]) : "f"(xv.y));
            asm("mov.b64 %0, {%1, %1};" : "=l"(xp[2]) : "f"(xv.z));
            asm("mov.b64 %0, {%1, %1};" : "=l"(xp[3]) : "f"(xv.w));
#pragma unroll
            for (int j2 = 0; j2 < 5; ++j2) {
                unsigned long long wp =
                    *(const unsigned long long*)&Ws[k][oi * 10 + 2 * j2];  // LDS.64 broadcast
#pragma unroll
                for (int i2 = 0; i2 < 4; ++i2)
                    asm("fma.rn.f32x2 %0, %1, %2, %0;" : "+l"(accp[i2][j2])
                        : "l"(xp[i2]), "l"(wp));
            }
        }
        __syncthreads();
    }
#pragma unroll
    for (int i2 = 0; i2 < 4; ++i2) {
        int node = nb + ni * 4 + i2;
        if (node < NN) {
#pragma unroll
            for (int j2 = 0; j2 < 5; ++j2) {
                float lo, hi;
                asm("mov.b64 {%0, %1}, %2;" : "=f"(lo), "=f"(hi) : "l"(accp[i2][j2]));
#pragma unroll
                for (int s = 0; s < 2; ++s) {
                    int o = oi * 10 + 2 * j2 + s;
                    float val = (s == 0 ? lo : hi) + g_b1[o];
                    if (o < 150) {
                        int sec = o >= 100 ? 2 : (o >= 50 ? 1 : 0);
                        int idx = o - sec * 50;
                        g_nlh[(size_t)node * 192 + sec * 64 + idx] = __float2half_rn(val);
                    } else if (o < 155) {
                        g_xr1[node * 5 + (o - 150)] = val;
                    }
                }
            }
        }
    }
}

// ---------------- K2: conv1 fused edge pass (R14 proven version) ----------------------
__global__ __launch_bounds__(256) void k_edge1(const float* __restrict__ ea_g,
                                               const int* __restrict__ eidx) {
    __shared__ float sEA[256 * 33];
    int tid = threadIdx.x;
    int e0 = blockIdx.x * 256;
    for (int i = tid; i < 256 * 32; i += 256) {
        float v = __ldcs(&ea_g[(size_t)e0 * 32 + i]);
        sEA[(i >> 5) * 33 + (i & 31)] = v;
    }
    __syncthreads();
    int e = e0 + tid;              // EE == 6250*256, no partial block
    int src = eidx[e], dst = eidx[EE + e];
    // ea as 16 packed f32x2 pairs
    unsigned long long ea2[16];
#pragma unroll
    for (int t = 0; t < 16; ++t) {
        float lo = sEA[tid * 33 + 2 * t];
        float hi = sEA[tid * 33 + 2 * t + 1];
        asm("mov.b64 %0, {%1, %2};" : "=l"(ea2[t]) : "f"(lo), "f"(hi));
    }

    // e2 for conv2 -> fp16 interleaved (32B per edge, 2x STG.128)
    {
        __half2 hp[8];
        float prev = 0.f;
#pragma unroll
        for (int h = 0; h < NH; ++h) {
            float a = cdot32(&c_e2W[h * 32], ea2);
            if (h & 1) hp[h >> 1] = __floats2half2_rn(prev, a);
            prev = a;
        }
        hp[5] = __floats2half2_rn(0.f, 0.f);
        hp[6] = hp[5];
        hp[7] = hp[5];
        const uint4* pw = (const uint4*)hp;
        uint4* dstp = (uint4*)(g_e2h + (size_t)e * 16);
        __stcs(dstp, pw[0]);
        __stcs(dstp + 1, pw[1]);
    }

    const __half* hq = g_nlh + (size_t)dst * 192;        // q @ 0
    const __half* hk = g_nlh + (size_t)src * 192 + 64;   // k @ 64
    const __half* hv = g_nlh + (size_t)src * 192 + 128;  // v @ 128

#pragma unroll
    for (int ch = 0; ch < 2; ++ch) {
        const int s0 = (ch == 0) ? 0 : 24;  // first half index of 32-half window (16B aligned)
        const int h0 = ch * 5;
        // e1 for heads h0..h0+4 (constant-bank weights, packed f32x2 MACs)
        float e1c[25];
#pragma unroll
        for (int i = 0; i < 25; ++i)
            e1c[i] = cdot32(&c_e1W[(h0 * 5 + i) * 32], ea2);
        float ex[5];
        {
            float qa[32], ka[32];
            ldh32(hq + s0, qa);
            ldh32(hk + s0, ka);
#pragma unroll
            for (int hc = 0; hc < 5; ++hc) {
                int li0 = (h0 + hc) * 5 - s0;
                float a = 0.f;
#pragma unroll
                for (int c = 0; c < 5; ++c)
                    a = fmaf(qa[li0 + c], ka[li0 + c] + e1c[hc * 5 + c], a);
                ex[hc] = __expf(a * 0.4472135954999579f);  // 1/sqrt(5); no max: exp safe
            }
        }
        {
            float va[32];
            ldh32(hv + s0, va);
            float n4s[5];
#pragma unroll
            for (int hc = 0; hc < 5; ++hc) {
                int li0 = (h0 + hc) * 5 - s0;
                float n0 = ex[hc] * (va[li0 + 0] + e1c[hc * 5 + 0]);
                float n1 = ex[hc] * (va[li0 + 1] + e1c[hc * 5 + 1]);
                float n2 = ex[hc] * (va[li0 + 2] + e1c[hc * 5 + 2]);
                float n3 = ex[hc] * (va[li0 + 3] + e1c[hc * 5 + 3]);
                n4s[hc]  = ex[hc] * (va[li0 + 4] + e1c[hc * 5 + 4]);
                redAdd4(&g_acc1A[((size_t)dst * NH + h0 + hc) * 4], n0, n1, n2, n3);
            }
            float* B = g_acc1B + (size_t)dst * 24;
            if (ch == 0) {
                redAdd4(B + 0, n4s[0], ex[0], n4s[1], ex[1]);   // heads 0,1
                redAdd4(B + 4, n4s[2], ex[2], n4s[3], ex[3]);   // heads 2,3
                redAdd2(B + 8, n4s[4], ex[4]);                  // head 4
            } else {
                redAdd2(B + 10, n4s[0], ex[0]);                 // head 5
                redAdd4(B + 12, n4s[1], ex[1], n4s[2], ex[2]);  // heads 6,7
                redAdd4(B + 16, n4s[3], ex[3], n4s[4], ex[4]);  // heads 8,9
            }
        }
    }
}

// ---------------- K3: conv1 node finish (head mean, beta gate) + GN sums ----------------
__global__ void k_node1(const float* __restrict__ b1W, const int* __restrict__ batch) {
    int n = blockIdx.x * 256 + threadIdx.x;
    if (n >= NN) return;
    float out[5] = {0.f, 0.f, 0.f, 0.f, 0.f};
    const float* A = g_acc1A + (size_t)n * 40;
    const float* B = g_acc1B + (size_t)n * 24;
#pragma unroll
    for (int h = 0; h < NH; ++h) {
        float d = B[h * 2 + 1];
        float inv = d > 0.f ? 1.f / d : 0.f;
#pragma unroll
        for (int c = 0; c < 4; ++c) out[c] += A[h * 4 + c] * inv;
        out[4] += B[h * 2] * inv;
    }
    float xr[5];
#pragma unroll
    for (int c = 0; c < 5; ++c) { out[c] *= 0.1f; xr[c] = g_xr1[n * 5 + c]; }
    float z = 0.f;
#pragma unroll
    for (int c = 0; c < 5; ++c)
        z += out[c] * b1W[c] + xr[c] * b1W[5 + c] + (out[c] - xr[c]) * b1W[10 + c];
    float beta = 1.f / (1.f + __expf(-z));
    int g = batch[n];
#pragma unroll
    for (int c = 0; c < 5; ++c) {
        float hv = beta * xr[c] + (1.f - beta) * out[c];
        g_h1[n * 5 + c] = hv;
        atomicAdd(&g_gsum[g * 8 + c], hv);
    }
    atomicAdd(&g_gsum[g * 8 + 5], 1.f);
}

// ---------------- K4: GraphNorm center + var sums ----------------
__global__ void k_gn_var(const int* __restrict__ batch, const float* __restrict__ gnms) {
    int n = blockIdx.x * 256 + threadIdx.x;
    if (n >= NN) return;
    int g = batch[n];
    float cnt = fmaxf(g_gsum[g * 8 + 5], 1.f);
    float inv = 1.f / cnt;
#pragma unroll
    for (int c = 0; c < 5; ++c) {
        float mean = g_gsum[g * 8 + c] * inv;
        float t = g_h1[n * 5 + c] - mean * gnms[c];
        g_h1[n * 5 + c] = t;
        atomicAdd(&g_gvar[g * 8 + c], t * t);
    }
}

// ---------------- K5: GraphNorm apply + ReLU + node linear 2 (fp16 table) --------------
// slots: q -> o (0..9), k -> o+6 (16..25), v -> o+6 (26..35), xr -> g_xr2
__global__ void k_node2(const int* __restrict__ batch, const float* __restrict__ gnW,
                        const float* __restrict__ gnb) {
    __shared__ float sw[160];
    __shared__ float sb[32];
    int tid = threadIdx.x;
    if (tid < 155) sw[tid] = g_w2[tid];
    if (tid < 31) sb[tid] = g_b2[tid];
    __syncthreads();
    int n = blockIdx.x * 256 + tid;
    if (n >= NN) return;
    int g = batch[n];
    float cnt = fmaxf(g_gsum[g * 8 + 5], 1.f);
    float hn[5];
#pragma unroll
    for (int c = 0; c < 5; ++c) {
        float var = g_gvar[g * 8 + c] / cnt;
        float t = g_h1[n * 5 + c];
        float y = gnW[c] * t * rsqrtf(var + 1e-5f) + gnb[c];
        hn[c] = fmaxf(y, 0.f);
    }
    __half* nt = g_nl2h + (size_t)n * 64;
#pragma unroll
    for (int o = 0; o < 31; ++o) {
        float a = sb[o];
#pragma unroll
        for (int c = 0; c < 5; ++c) a = fmaf(sw[o * 5 + c], hn[c], a);
        if (o < 30) {
            int slot = (o < 10) ? o : o + 6;   // q@0..9, k@16..25, v@26..35
            nt[slot] = __float2half_rn(a);
        } else {
            g_xr2[n] = a;
        }
    }
}

// ---------------- K6: conv2 fused edge pass (contiguous k+v window, 7 LDG) -------------
__global__ __launch_bounds__(256) void k_edge2(const int* __restrict__ eidx) {
    int e = blockIdx.x * 256 + threadIdx.x;
    int src = eidx[e], dst = eidx[EE + e];
    float qa[16], kv[24], ez[16];
    ldh16(g_nl2h + (size_t)dst * 64, qa);        // q line of dst
    ldh24(g_nl2h + (size_t)src * 64 + 16, kv);   // k = kv[0..9], v = kv[10..19]
    {
        const uint4* ep = (const uint4*)(g_e2h + (size_t)e * 16);
        uint4 r0 = __ldcs(ep);
        uint4 r1 = __ldcs(ep + 1);
        const __half2* h0 = (const __half2*)&r0;
        const __half2* h1 = (const __half2*)&r1;
#pragma unroll
        for (int j = 0; j < 4; ++j) {
            float2 f = __half22float2(h0[j]);
            ez[2 * j] = f.x; ez[2 * j + 1] = f.y;
            float2 g = __half22float2(h1[j]);
            ez[8 + 2 * j] = g.x; ez[8 + 2 * j + 1] = g.y;
        }
    }
    float* acc = g_acc2p + (size_t)dst * 24;
#pragma unroll
    for (int h = 0; h < NH; h += 2) {
        float ex0 = __expf(qa[h] * (kv[h] + ez[h]));          // c=1 scale; exp safe
        float n0 = ex0 * (kv[10 + h] + ez[h]);
        float ex1 = __expf(qa[h + 1] * (kv[h + 1] + ez[h + 1]));
        float n1 = ex1 * (kv[11 + h] + ez[h + 1]);
        redAdd4(acc + h * 2, n0, ex0, n1, ex1);
    }
}

// ---------------- K7: final (head mean, beta gate, sigmoid) ----------------
__global__ void k_final(const float* __restrict__ b2W, float* __restrict__ outp) {
    int n = blockIdx.x * 256 + threadIdx.x;
    if (n >= NN) return;
    float s = 0.f;
    const float* acc = g_acc2p + (size_t)n * 24;
#pragma unroll
    for (int h = 0; h < NH; ++h) {
        float num = acc[h * 2 + 0];
        float d = acc[h * 2 + 1];
        s += d > 0.f ? num / d : 0.f;
    }
    float out = s * 0.1f;
    float xr = g_xr2[n];
    float z = out * b2W[0] + xr * b2W[1] + (out - xr) * b2W[2];
    float beta = 1.f / (1.f + __expf(-z));
    float y = beta * xr + (1.f - beta) * out;
    outp[n] = 1.f / (1.f + __expf(-y));
}

// ---------------- launch ----------------
extern "C" void kernel_launch(void* const* d_in, const int* in_sizes, int n_in,
                              void* d_out, int out_size) {
    (void)in_sizes; (void)n_in; (void)out_size;
    const float* x    = (const float*)d_in[0];
    const float* ea   = (const float*)d_in[1];
    const int*   eidx = (const int*)d_in[2];
    const int*   batch= (const int*)d_in[3];
    const float* q1W = (const float*)d_in[4];  const float* q1b = (const float*)d_in[5];
    const float* k1W = (const float*)d_in[6];  const float* k1b = (const float*)d_in[7];
    const float* v1W = (const float*)d_in[8];  const float* v1b = (const float*)d_in[9];
    const float* e1W = (const float*)d_in[10];
    const float* s1W = (const float*)d_in[11]; const float* s1b = (const float*)d_in[12];
    const float* b1W = (const float*)d_in[13];
    const float* gnW = (const float*)d_in[14]; const float* gnb = (const float*)d_in[15];
    const float* gnms= (const float*)d_in[16];
    const float* q2W = (const float*)d_in[17]; const float* q2b = (const float*)d_in[18];
    const float* k2W = (const float*)d_in[19]; const float* k2b = (const float*)d_in[20];
    const float* v2W = (const float*)d_in[21]; const float* v2b = (const float*)d_in[22];
    const float* e2W = (const float*)d_in[23];
    const float* s2W = (const float*)d_in[24]; const float* s2b = (const float*)d_in[25];
    const float* b2W = (const float*)d_in[26];
    float* outp = (float*)d_out;

    // fill constant bank (graph-capturable D2D memcpy nodes)
    cudaMemcpyToSymbolAsync(c_e1W, e1W, 1600 * sizeof(float), 0, cudaMemcpyDeviceToDevice);
    cudaMemcpyToSymbolAsync(c_e2W, e2W, 320 * sizeof(float), 0, cudaMemcpyDeviceToDevice);

    k_pack<<<80, 256>>>(q1W, q1b, k1W, k1b, v1W, v1b, s1W, s1b,
                        q2W, q2b, k2W, k2b, v2W, v2b, s2W, s2b);
    k_init<<<2048, 256>>>();
    k_lin1<<<(NN + 63) / 64, 256>>>(x);
    k_edge1<<<EE / 256, 256>>>(ea, eidx);
    k_node1<<<(NN + 255) / 256, 256>>>(b1W, batch);
    k_gn_var<<<(NN + 255) / 256, 256>>>(batch, gnms);
    k_node2<<<(NN + 255) / 256, 256>>>(batch, gnW, gnb);
    k_edge2<<<EE / 256, 256>>>(eidx);
    k_final<<<(NN + 255) / 256, 256>>>(b2W, outp);
}